// round 13
// baseline (speedup 1.0000x reference)
#include <cuda_runtime.h>
#include <cstdint>

#define Bb 64
#define Tt 1024
#define Ii 64
#define Hh 512
#define G3 1536
#define MM (Bb*Tt)      // 65536 rows
#define NGX 18          // xg1 gemm-worker blocks

// ---------------- scratch (device globals: allocation-free) ----------------
__device__ float g_xg0[(size_t)MM * G3];   // layer-0 input gates (time-major rows t*B+b)
__device__ float g_xg1[(size_t)MM * G3];   // layer-1 input gates (time-major)
__device__ float g_y0 [(size_t)MM * Hh];   // layer-0 hidden history (time-major)
__device__ float g_y1 [(size_t)MM * Hh];   // layer-1 hidden history (time-major)

struct __align__(128) PadFlag { unsigned v; unsigned pad[31]; };
__device__ PadFlag g_hf[2][2][32];   // [layer][grp][hb] step flags (zeroed per launch)
__device__ unsigned g_xf[Tt];        // xg1[t] ready flags (zeroed per launch)

// ---------------- helpers ----------------
__device__ __forceinline__ float to_tf32(float x) {
    unsigned u;
    asm("cvt.rna.tf32.f32 %0, %1;" : "=r"(u) : "f"(x));
    return __uint_as_float(u);
}

__device__ __forceinline__ void mma_tf32(float* c, const unsigned* a, unsigned b0, unsigned b1) {
    asm("mma.sync.aligned.m16n8k8.row.col.f32.tf32.tf32.f32 "
        "{%0,%1,%2,%3},{%4,%5,%6,%7},{%8,%9},{%0,%1,%2,%3};"
        : "+f"(c[0]), "+f"(c[1]), "+f"(c[2]), "+f"(c[3])
        : "r"(a[0]), "r"(a[1]), "r"(a[2]), "r"(a[3]), "r"(b0), "r"(b1));
}

__device__ __forceinline__ unsigned smem_u32(const void* p) {
    return (unsigned)__cvta_generic_to_shared(p);
}

__device__ __forceinline__ void waitflag(const unsigned* p, unsigned tgt) {
    unsigned v;
    do {
        asm volatile("ld.global.acquire.gpu.b32 %0, [%1];" : "=r"(v) : "l"(p) : "memory");
    } while ((int)(v - tgt) < 0);
}

// ---------------- flag reset (runs before megakernel every launch) ----------
__global__ void zero_flags() {
    int tid = threadIdx.x;
    if (tid < 128) ((PadFlag*)g_hf)[tid].v = 0;
    for (int i = tid; i < Tt; i += 256) g_xf[i] = 0;
}

// ---------------- generic tf32 GEMM (xg0 + FC): C = A @ W^T + bias ----------
// mode: output row remap. 0: ro=m  1: m=(b*T+t) -> ro=t*B+b   2: m=(t*B+b) -> ro=b*T+t
__global__ __launch_bounds__(256) void gemm_tf32(
    const float* __restrict__ A, const float* __restrict__ W,
    const float* __restrict__ bias, float* __restrict__ C,
    int M, int N, int K, int mode)
{
    __shared__ float As[128][20];
    __shared__ float Ws[64][20];
    const int tid  = threadIdx.x;
    const int warp = tid >> 5, lane = tid & 31;
    const int gID  = lane >> 2, tig = lane & 3;
    const int wm   = warp >> 1, wn = warp & 1;
    const int m0   = blockIdx.y * 128, n0 = blockIdx.x * 64;

    float acc[2][4][4];
    #pragma unroll
    for (int i = 0; i < 2; i++)
        #pragma unroll
        for (int j = 0; j < 4; j++)
            #pragma unroll
            for (int q = 0; q < 4; q++) acc[i][j][q] = 0.f;

    for (int k0 = 0; k0 < K; k0 += 16) {
        #pragma unroll
        for (int i = 0; i < 2; i++) {
            int idx = tid + i * 256;
            int r = idx >> 2, cb = idx & 3;
            float4 v = *(const float4*)(A + (size_t)(m0 + r) * K + k0 + cb * 4);
            *(float4*)(&As[r][cb * 4]) =
                make_float4(to_tf32(v.x), to_tf32(v.y), to_tf32(v.z), to_tf32(v.w));
        }
        {
            int r = tid >> 2, cb = tid & 3;
            float4 v = *(const float4*)(W + (size_t)(n0 + r) * K + k0 + cb * 4);
            *(float4*)(&Ws[r][cb * 4]) =
                make_float4(to_tf32(v.x), to_tf32(v.y), to_tf32(v.z), to_tf32(v.w));
        }
        __syncthreads();
        #pragma unroll
        for (int s = 0; s < 2; s++) {
            const int kk = s * 8;
            unsigned a[2][4];
            #pragma unroll
            for (int mt = 0; mt < 2; mt++) {
                int r = wm * 32 + mt * 16 + gID;
                a[mt][0] = __float_as_uint(As[r][kk + tig]);
                a[mt][1] = __float_as_uint(As[r + 8][kk + tig]);
                a[mt][2] = __float_as_uint(As[r][kk + tig + 4]);
                a[mt][3] = __float_as_uint(As[r + 8][kk + tig + 4]);
            }
            #pragma unroll
            for (int nt = 0; nt < 4; nt++) {
                int n = wn * 32 + nt * 8 + gID;
                unsigned b0 = __float_as_uint(Ws[n][kk + tig]);
                unsigned b1 = __float_as_uint(Ws[n][kk + tig + 4]);
                #pragma unroll
                for (int mt = 0; mt < 2; mt++)
                    mma_tf32(acc[mt][nt], a[mt], b0, b1);
            }
        }
        __syncthreads();
    }
    #pragma unroll
    for (int mt = 0; mt < 2; mt++) {
        #pragma unroll
        for (int rr = 0; rr < 2; rr++) {
            int r = m0 + wm * 32 + mt * 16 + rr * 8 + gID;
            int ro = (mode == 0) ? r
                   : (mode == 1) ? ((r & (Tt - 1)) * Bb + (r >> 10))
                                 : ((r & (Bb - 1)) * Tt + (r >> 6));
            #pragma unroll
            for (int nt = 0; nt < 4; nt++) {
                int c = n0 + wn * 32 + nt * 8 + tig * 2;
                C[(size_t)ro * N + c]     = acc[mt][nt][rr * 2]     + bias[c];
                C[(size_t)ro * N + c + 1] = acc[mt][nt][rr * 2 + 1] + bias[c + 1];
            }
        }
    }
}

// ---------------- recurrent role (32-batch groups, 64 blocks per layer) ----
// rb: 0..63 -> grp = rb>>5 (32 batches), hb = rb&31 (16 units).
// smem layout: stage[8][4][32][20] | own[32][20] | part[8][32][49] | b_s[48]
#define ST_F   (8*4*32*20)
#define OWN_F  (32*20)
#define PART_F (8*32*49)

__device__ __forceinline__ void rec_role(
    int L, int rb, float* sm,
    const float* __restrict__ xg, const float* __restrict__ whh,
    const float* __restrict__ bhh, float* __restrict__ y)
{
    float* stage = sm;
    float* own   = sm + ST_F;
    float* part  = own + OWN_F;
    float* b_s   = part + PART_F;

    const int grp = rb >> 5, hb = rb & 31;
    const int tid  = threadIdx.x;
    const int warp = tid >> 5, lane = tid & 31;
    const int gID  = lane >> 2, tig = lane & 3;
    const int bb   = tid >> 4, uu = tid & 15;
    const int bglob = grp * 32;
    const int k0w  = warp * 64;
    const int c0   = warp * 4;

    // W_hh fragments into registers (tf32-rounded), 48 gate rows x this warp's k=64
    unsigned breg[8][6][2];
    #pragma unroll
    for (int nt = 0; nt < 6; nt++) {
        int r = nt * 8 + gID;                          // 0..47
        int grow = (r >> 4) * Hh + hb * 16 + (r & 15);
        const float* wrow = whh + (size_t)grow * Hh;
        #pragma unroll
        for (int ks = 0; ks < 8; ks++) {
            int k = k0w + ks * 8 + tig;
            breg[ks][nt][0] = __float_as_uint(to_tf32(wrow[k]));
            breg[ks][nt][1] = __float_as_uint(to_tf32(wrow[k + 4]));
        }
    }
    if (tid < 48) b_s[tid] = bhh[(tid >> 4) * Hh + hb * 16 + (tid & 15)];
    __syncthreads();

    const int ug = hb * 16 + uu;
    float hprev[2] = {0.f, 0.f};

    for (int t = 0; t < Tt; t++) {
        // layer-1: wait until xg1[t] tile is published by the gemm workers
        if (L == 1) {
            if (lane == 0) waitflag(&g_xf[t], 1u);
            __syncwarp();
        }
        // prefetch input-side gates (2 batches per thread)
        const size_t xb0 = ((size_t)t * Bb + bglob + bb) * (size_t)G3;
        const size_t xb1 = xb0 + (size_t)16 * G3;
        float xr0 = __ldg(xg + xb0 + ug);
        float xz0 = __ldg(xg + xb0 + Hh + ug);
        float xn0 = __ldg(xg + xb0 + 2 * Hh + ug);
        float xr1 = __ldg(xg + xb1 + ug);
        float xz1 = __ldg(xg + xb1 + Hh + ug);
        float xn1 = __ldg(xg + xb1 + 2 * Hh + ug);

        float acc[2][6][4];
        #pragma unroll
        for (int mt = 0; mt < 2; mt++)
            #pragma unroll
            for (int nt = 0; nt < 6; nt++)
                acc[mt][nt][0]=acc[mt][nt][1]=acc[mt][nt][2]=acc[mt][nt][3]=0.f;

        if (t > 0) {
            const float* ybase = y + ((size_t)(t - 1) * Bb + bglob) * Hh;
            // lanes 0-3 poll the 4 producer flags in parallel
            if (lane < 4) {
                int j = c0 + lane;
                if (j != hb) waitflag(&g_hf[L][grp][j].v, (unsigned)t);
            }
            __syncwarp();
            // bulk-load all chunks (32 rows x 64B each), own chunk from smem
            #pragma unroll
            for (int c = 0; c < 4; c++) {
                int j = c0 + c;
                if (j != hb) {
                    #pragma unroll
                    for (int i = 0; i < 4; i++) {
                        int idx = lane + 32 * i;
                        int row = idx >> 2, seg = idx & 3;
                        const float* src = ybase + (size_t)row * Hh + j * 16 + seg * 4;
                        float* dst = stage + (((warp * 4 + c) * 32 + row) * 20 + seg * 4);
                        asm volatile("cp.async.cg.shared.global [%0], [%1], 16;"
                                     :: "r"(smem_u32(dst)), "l"(src) : "memory");
                    }
                }
            }
            asm volatile("cp.async.commit_group;\n\tcp.async.wait_group 0;" ::: "memory");
            __syncwarp();

            #pragma unroll
            for (int c = 0; c < 4; c++) {
                const float* st = (c0 + c == hb) ? own
                                : stage + ((warp * 4 + c) * 32 * 20);
                #pragma unroll
                for (int s = 0; s < 2; s++) {
                    const int kk = s * 8;
                    #pragma unroll
                    for (int mt = 0; mt < 2; mt++) {
                        unsigned a[4];
                        int r0 = gID + 16 * mt;
                        a[0] = __float_as_uint(st[r0 * 20 + kk + tig]);
                        a[1] = __float_as_uint(st[(r0 + 8) * 20 + kk + tig]);
                        a[2] = __float_as_uint(st[r0 * 20 + kk + tig + 4]);
                        a[3] = __float_as_uint(st[(r0 + 8) * 20 + kk + tig + 4]);
                        #pragma unroll
                        for (int nt = 0; nt < 6; nt++)
                            mma_tf32(acc[mt][nt], a, breg[c * 2 + s][nt][0], breg[c * 2 + s][nt][1]);
                    }
                }
            }
        }

        // partials to smem: part[warp][32 batch][48 gate-rows]
        float* pw = part + warp * 32 * 49;
        #pragma unroll
        for (int mt = 0; mt < 2; mt++)
            #pragma unroll
            for (int nt = 0; nt < 6; nt++) {
                int c = nt * 8 + tig * 2;
                int r0 = gID + 16 * mt;
                pw[r0 * 49 + c]           = acc[mt][nt][0];
                pw[r0 * 49 + c + 1]       = acc[mt][nt][1];
                pw[(r0 + 8) * 49 + c]     = acc[mt][nt][2];
                pw[(r0 + 8) * 49 + c + 1] = acc[mt][nt][3];
            }
        __syncthreads();

        // gate phase: 2 (batch, unit) outputs per thread; fold 8-way k-reduction
        #pragma unroll
        for (int half = 0; half < 2; half++) {
            int bbx = bb + 16 * half;
            float hr = b_s[uu], hz = b_s[16 + uu], hn = b_s[32 + uu];
            #pragma unroll
            for (int w = 0; w < 8; w++) {
                const float* p = part + (w * 32 + bbx) * 49;
                hr += p[uu]; hz += p[16 + uu]; hn += p[32 + uu];
            }
            float xr = half ? xr1 : xr0, xz = half ? xz1 : xz0, xn = half ? xn1 : xn0;
            float ar = xr + hr; ar = fminf(fmaxf(ar, -30.f), 30.f);
            float az = xz + hz; az = fminf(fmaxf(az, -30.f), 30.f);
            float r = __fdividef(1.f, 1.f + __expf(-ar));
            float z = __fdividef(1.f, 1.f + __expf(-az));
            float an = xn + r * hn; an = fminf(fmaxf(an, -15.f), 15.f);
            float n = 1.f - __fdividef(2.f, __expf(2.f * an) + 1.f);
            float hnew = (1.f - z) * n + z * hprev[half];
            float hro = to_tf32(hnew);
            hprev[half] = hro;
            y[((size_t)t * Bb + bglob + bbx) * Hh + ug] = hro;
            own[bbx * 20 + uu] = hro;
        }

        __syncthreads();
        if (tid == 0) {
            unsigned nv = (unsigned)t + 1u;
            asm volatile("st.global.release.gpu.b32 [%0], %1;"
                         :: "l"(&g_hf[L][grp][hb].v), "r"(nv) : "memory");
        }
    }
}

// ---------------- xg1 gemm-worker role: stream xg1[t] = y0[t] @ w_ih1^T + b --
// One block computes the full 64x1536 tile for one t. 18 blocks stride over t.
// smem: As[64][516] (full y0[t], tf32-valued already) | Ws[64][132] (k-chunk 128)
__device__ void gemmx_role(int gb, float* sm,
                           const float* __restrict__ wih1,
                           const float* __restrict__ bih1)
{
    float* As = sm;                 // 64*516
    float* Ws = sm + 64 * 516;      // 64*132
    const int tid  = threadIdx.x;
    const int warp = tid >> 5, lane = tid & 31;
    const int gID  = lane >> 2, tig = lane & 3;
    const int wm   = warp >> 2, wn = warp & 3;

    for (int t = gb; t < Tt; t += NGX) {
        // wait for y0[t]: all 64 layer-0 block flags >= t+1
        if (tid < 64) waitflag(&g_hf[0][tid >> 5][tid & 31].v, (unsigned)(t + 1));
        __syncthreads();

        // load full A = y0[t] (64 x 512)
        const float* ysrc = g_y0 + (size_t)t * Bb * Hh;
        #pragma unroll
        for (int i = 0; i < 32; i++) {
            int idx = tid + i * 256;
            int r = idx >> 7, cb = idx & 127;
            *(float4*)(As + r * 516 + cb * 4) = *(const float4*)(ysrc + (size_t)r * Hh + cb * 4);
        }
        __syncthreads();

        for (int n0 = 0; n0 < 24; n0++) {
            float acc[2][2][4];
            #pragma unroll
            for (int mt = 0; mt < 2; mt++)
                #pragma unroll
                for (int nt = 0; nt < 2; nt++)
                    acc[mt][nt][0]=acc[mt][nt][1]=acc[mt][nt][2]=acc[mt][nt][3]=0.f;

            for (int kc = 0; kc < 4; kc++) {
                // load W chunk: 64 rows x 128 k (tf32-rounded)
                #pragma unroll
                for (int i = 0; i < 8; i++) {
                    int idx = tid + i * 256;
                    int r = idx >> 5, cb = idx & 31;
                    float4 v = *(const float4*)(wih1 + (size_t)(n0 * 64 + r) * Hh + kc * 128 + cb * 4);
                    *(float4*)(Ws + r * 132 + cb * 4) =
                        make_float4(to_tf32(v.x), to_tf32(v.y), to_tf32(v.z), to_tf32(v.w));
                }
                __syncthreads();
                #pragma unroll
                for (int ks = 0; ks < 16; ks++) {
                    int kA = kc * 128 + ks * 8, kW = ks * 8;
                    unsigned a[2][4];
                    #pragma unroll
                    for (int mt = 0; mt < 2; mt++) {
                        int r = wm * 32 + mt * 16 + gID;
                        a[mt][0] = __float_as_uint(As[r * 516 + kA + tig]);
                        a[mt][1] = __float_as_uint(As[(r + 8) * 516 + kA + tig]);
                        a[mt][2] = __float_as_uint(As[r * 516 + kA + tig + 4]);
                        a[mt][3] = __float_as_uint(As[(r + 8) * 516 + kA + tig + 4]);
                    }
                    #pragma unroll
                    for (int nt = 0; nt < 2; nt++) {
                        int nr = wn * 16 + nt * 8 + gID;
                        unsigned b0 = __float_as_uint(Ws[nr * 132 + kW + tig]);
                        unsigned b1 = __float_as_uint(Ws[nr * 132 + kW + tig + 4]);
                        #pragma unroll
                        for (int mt = 0; mt < 2; mt++)
                            mma_tf32(acc[mt][nt], a[mt], b0, b1);
                    }
                }
                __syncthreads();
            }
            // epilogue: write xg1 rows (t*64 + m)
            #pragma unroll
            for (int mt = 0; mt < 2; mt++)
                #pragma unroll
                for (int rr = 0; rr < 2; rr++) {
                    int m = wm * 32 + mt * 16 + rr * 8 + gID;
                    #pragma unroll
                    for (int nt = 0; nt < 2; nt++) {
                        int n = n0 * 64 + wn * 16 + nt * 8 + tig * 2;
                        g_xg1[((size_t)t * Bb + m) * G3 + n]     = acc[mt][nt][rr * 2]     + bih1[n];
                        g_xg1[((size_t)t * Bb + m) * G3 + n + 1] = acc[mt][nt][rr * 2 + 1] + bih1[n + 1];
                    }
                }
        }
        __syncthreads();
        if (tid == 0)
            asm volatile("st.global.release.gpu.b32 [%0], %1;"
                         :: "l"(&g_xf[t]), "r"(1u) : "memory");
    }
}

// ---------------- megakernel: 64 L0-rec + 64 L1-rec + 18 xg1-workers -------
#define MEGA_SMEM ((64*516 + 64*132) * 4)   // 165,888 B (> rec's 134,848)

__global__ __launch_bounds__(256, 1) void gru_mega(
    const float* __restrict__ whh0, const float* __restrict__ bhh0,
    const float* __restrict__ whh1, const float* __restrict__ bhh1,
    const float* __restrict__ wih1, const float* __restrict__ bih1)
{
    extern __shared__ float sm[];
    int bid = blockIdx.x;
    if (bid < 64)       rec_role(0, bid,      sm, g_xg0, whh0, bhh0, g_y0);
    else if (bid < 128) rec_role(1, bid - 64, sm, g_xg1, whh1, bhh1, g_y1);
    else                gemmx_role(bid - 128, sm, wih1, bih1);
}

// ---------------- launch ----------------
extern "C" void kernel_launch(void* const* d_in, const int* in_sizes, int n_in,
                              void* d_out, int out_size)
{
    const float* x    = (const float*)d_in[0];
    const float* wih0 = (const float*)d_in[1];
    const float* whh0 = (const float*)d_in[2];
    const float* bih0 = (const float*)d_in[3];
    const float* bhh0 = (const float*)d_in[4];
    const float* wih1 = (const float*)d_in[5];
    const float* whh1 = (const float*)d_in[6];
    const float* bih1 = (const float*)d_in[7];
    const float* bhh1 = (const float*)d_in[8];
    const float* fcw  = (const float*)d_in[9];
    const float* fcb  = (const float*)d_in[10];
    float* out = (float*)d_out;

    float *xg0p = 0, *y1p = 0;
    cudaGetSymbolAddress((void**)&xg0p, g_xg0);
    cudaGetSymbolAddress((void**)&y1p,  g_y1);

    cudaFuncSetAttribute(gru_mega, cudaFuncAttributeMaxDynamicSharedMemorySize, MEGA_SMEM);

    // reset all flags (makes the megakernel replay-safe with absolute targets)
    zero_flags<<<1, 256>>>();
    // xg0 = x @ w_ih0^T + b_ih0, written time-major (mode 1)
    gemm_tf32<<<dim3(G3 / 64, MM / 128), 256>>>(x, wih0, bih0, xg0p, MM, G3, Ii, 1);
    // fused: layer-0 rec || xg1 streaming gemm || layer-1 rec
    gru_mega<<<64 + 64 + NGX, 256, MEGA_SMEM>>>(whh0, bhh0, whh1, bhh1, wih1, bih1);
    // FC: y1 rows (t*B+b) -> out rows (b*T+t)  (mode 2)
    gemm_tf32<<<dim3(Ii / 64, MM / 128), 256>>>(y1p, fcw, fcb, out, MM, Ii, Hh, 2);
}

// round 14
// speedup vs baseline: 1.1954x; 1.1954x over previous
#include <cuda_runtime.h>
#include <cstdint>

#define Bb 64
#define Tt 1024
#define Ii 64
#define Hh 512
#define G3 1536
#define MM (Bb*Tt)      // 65536 rows
#define NWK 82          // xg1 gemm-worker blocks (32+32+82 = 146 <= 148 SMs)

// ---------------- scratch (device globals: allocation-free) ----------------
__device__ float g_xg0[(size_t)MM * G3];   // layer-0 input gates (time-major rows t*B+b)
__device__ float g_xg1[(size_t)MM * G3];   // layer-1 input gates (time-major)
__device__ float g_y0 [(size_t)MM * Hh];   // layer-0 hidden history (time-major)
__device__ float g_y1 [(size_t)MM * Hh];   // layer-1 hidden history (time-major)

struct __align__(128) PadFlag { unsigned v; unsigned pad[31]; };
__device__ PadFlag g_hf[2][32];      // [layer][hb] step flags (zeroed per launch)
__device__ unsigned g_xf[Tt];        // xg1[t] ready flags (zeroed per launch)

// ---------------- helpers ----------------
__device__ __forceinline__ float to_tf32(float x) {
    unsigned u;
    asm("cvt.rna.tf32.f32 %0, %1;" : "=r"(u) : "f"(x));
    return __uint_as_float(u);
}

__device__ __forceinline__ void mma_tf32(float* c, const unsigned* a, unsigned b0, unsigned b1) {
    asm("mma.sync.aligned.m16n8k8.row.col.f32.tf32.tf32.f32 "
        "{%0,%1,%2,%3},{%4,%5,%6,%7},{%8,%9},{%0,%1,%2,%3};"
        : "+f"(c[0]), "+f"(c[1]), "+f"(c[2]), "+f"(c[3])
        : "r"(a[0]), "r"(a[1]), "r"(a[2]), "r"(a[3]), "r"(b0), "r"(b1));
}

__device__ __forceinline__ unsigned smem_u32(const void* p) {
    return (unsigned)__cvta_generic_to_shared(p);
}

__device__ __forceinline__ void waitflag(const unsigned* p, unsigned tgt) {
    unsigned v;
    do {
        asm volatile("ld.global.acquire.gpu.b32 %0, [%1];" : "=r"(v) : "l"(p) : "memory");
    } while ((int)(v - tgt) < 0);
}

// ---------------- flag reset (runs before megakernel every launch) ----------
__global__ void zero_flags() {
    int tid = threadIdx.x;
    if (tid < 64) ((PadFlag*)g_hf)[tid].v = 0;
    for (int i = tid; i < Tt; i += 256) g_xf[i] = 0;
}

// ---------------- generic tf32 GEMM (xg0 + FC): C = A @ W^T + bias ----------
// mode: output row remap. 0: ro=m  1: m=(b*T+t) -> ro=t*B+b   2: m=(t*B+b) -> ro=b*T+t
__global__ __launch_bounds__(256) void gemm_tf32(
    const float* __restrict__ A, const float* __restrict__ W,
    const float* __restrict__ bias, float* __restrict__ C,
    int M, int N, int K, int mode)
{
    __shared__ float As[128][20];
    __shared__ float Ws[64][20];
    const int tid  = threadIdx.x;
    const int warp = tid >> 5, lane = tid & 31;
    const int gID  = lane >> 2, tig = lane & 3;
    const int wm   = warp >> 1, wn = warp & 1;
    const int m0   = blockIdx.y * 128, n0 = blockIdx.x * 64;

    float acc[2][4][4];
    #pragma unroll
    for (int i = 0; i < 2; i++)
        #pragma unroll
        for (int j = 0; j < 4; j++)
            #pragma unroll
            for (int q = 0; q < 4; q++) acc[i][j][q] = 0.f;

    for (int k0 = 0; k0 < K; k0 += 16) {
        #pragma unroll
        for (int i = 0; i < 2; i++) {
            int idx = tid + i * 256;
            int r = idx >> 2, cb = idx & 3;
            float4 v = *(const float4*)(A + (size_t)(m0 + r) * K + k0 + cb * 4);
            *(float4*)(&As[r][cb * 4]) =
                make_float4(to_tf32(v.x), to_tf32(v.y), to_tf32(v.z), to_tf32(v.w));
        }
        {
            int r = tid >> 2, cb = tid & 3;
            float4 v = *(const float4*)(W + (size_t)(n0 + r) * K + k0 + cb * 4);
            *(float4*)(&Ws[r][cb * 4]) =
                make_float4(to_tf32(v.x), to_tf32(v.y), to_tf32(v.z), to_tf32(v.w));
        }
        __syncthreads();
        #pragma unroll
        for (int s = 0; s < 2; s++) {
            const int kk = s * 8;
            unsigned a[2][4];
            #pragma unroll
            for (int mt = 0; mt < 2; mt++) {
                int r = wm * 32 + mt * 16 + gID;
                a[mt][0] = __float_as_uint(As[r][kk + tig]);
                a[mt][1] = __float_as_uint(As[r + 8][kk + tig]);
                a[mt][2] = __float_as_uint(As[r][kk + tig + 4]);
                a[mt][3] = __float_as_uint(As[r + 8][kk + tig + 4]);
            }
            #pragma unroll
            for (int nt = 0; nt < 4; nt++) {
                int n = wn * 32 + nt * 8 + gID;
                unsigned b0 = __float_as_uint(Ws[n][kk + tig]);
                unsigned b1 = __float_as_uint(Ws[n][kk + tig + 4]);
                #pragma unroll
                for (int mt = 0; mt < 2; mt++)
                    mma_tf32(acc[mt][nt], a[mt], b0, b1);
            }
        }
        __syncthreads();
    }
    #pragma unroll
    for (int mt = 0; mt < 2; mt++) {
        #pragma unroll
        for (int rr = 0; rr < 2; rr++) {
            int r = m0 + wm * 32 + mt * 16 + rr * 8 + gID;
            int ro = (mode == 0) ? r
                   : (mode == 1) ? ((r & (Tt - 1)) * Bb + (r >> 10))
                                 : ((r & (Bb - 1)) * Tt + (r >> 6));
            #pragma unroll
            for (int nt = 0; nt < 4; nt++) {
                int c = n0 + wn * 32 + nt * 8 + tig * 2;
                C[(size_t)ro * N + c]     = acc[mt][nt][rr * 2]     + bias[c];
                C[(size_t)ro * N + c + 1] = acc[mt][nt][rr * 2 + 1] + bias[c + 1];
            }
        }
    }
}

// ---------------- recurrent role: 32 blocks per layer, m=64 batches --------
// Block hb produces units [16hb,16hb+16) for ALL 64 batches each step.
// Warp w consumes chunks 4w..4w+3 (its k=64 slice); full h staged in smem.
// MMA/gates processed as two m=32 halves sharing the part buffer.
#define ST_F   (32*64*20)    // stage: 32 chunks x 64 rows x (16+4pad)
#define OWN_F  (64*20)
#define PART_F (8*32*49)

__device__ __forceinline__ void rec_role(
    int L, int hb, float* sm,
    const float* __restrict__ xg, const float* __restrict__ whh,
    const float* __restrict__ bhh, float* __restrict__ y)
{
    float* stage = sm;
    float* own   = sm + ST_F;
    float* part  = own + OWN_F;
    float* b_s   = part + PART_F;

    const int tid  = threadIdx.x;
    const int warp = tid >> 5, lane = tid & 31;
    const int gID  = lane >> 2, tig = lane & 3;
    const int bb   = tid >> 4, uu = tid & 15;
    const int k0w  = warp * 64;
    const int c0   = warp * 4;

    // W_hh fragments into registers (tf32-rounded): 48 gate rows x this warp's k=64
    unsigned breg[8][6][2];
    #pragma unroll
    for (int nt = 0; nt < 6; nt++) {
        int r = nt * 8 + gID;                          // 0..47
        int grow = (r >> 4) * Hh + hb * 16 + (r & 15);
        const float* wrow = whh + (size_t)grow * Hh;
        #pragma unroll
        for (int ks = 0; ks < 8; ks++) {
            int k = k0w + ks * 8 + tig;
            breg[ks][nt][0] = __float_as_uint(to_tf32(wrow[k]));
            breg[ks][nt][1] = __float_as_uint(to_tf32(wrow[k + 4]));
        }
    }
    if (tid < 48) b_s[tid] = bhh[(tid >> 4) * Hh + hb * 16 + (tid & 15)];
    __syncthreads();

    const int ug = hb * 16 + uu;
    float hprev[4] = {0.f, 0.f, 0.f, 0.f};

    for (int t = 0; t < Tt; t++) {
        // layer-1: wait for the xg1[t] tile from the gemm workers
        if (L == 1) {
            if (lane == 0) waitflag(&g_xf[t], 1u);
            __syncwarp();
        }
        // prefetch input-side gates: 4 batches per thread (bb+16q)
        float xr[4], xz[4], xn[4];
        #pragma unroll
        for (int q = 0; q < 4; q++) {
            const size_t xb = ((size_t)t * Bb + bb + 16 * q) * (size_t)G3;
            xr[q] = __ldg(xg + xb + ug);
            xz[q] = __ldg(xg + xb + Hh + ug);
            xn[q] = __ldg(xg + xb + 2 * Hh + ug);
        }

        if (t > 0) {
            const float* ybase = y + (size_t)(t - 1) * Bb * Hh;
            // lanes 0-3 poll the 4 producer flags in parallel
            if (lane < 4) {
                int j = c0 + lane;
                if (j != hb) waitflag(&g_hf[L][j].v, (unsigned)t);
            }
            __syncwarp();
            // bulk-load this warp's 4 chunks (64 rows x 64B each); own from smem
            #pragma unroll
            for (int c = 0; c < 4; c++) {
                int j = c0 + c;
                if (j != hb) {
                    #pragma unroll
                    for (int i = 0; i < 8; i++) {
                        int idx = lane + 32 * i;
                        int row = idx >> 2, seg = idx & 3;
                        const float* src = ybase + (size_t)row * Hh + j * 16 + seg * 4;
                        float* dst = stage + ((size_t)(j * 64 + row)) * 20 + seg * 4;
                        asm volatile("cp.async.cg.shared.global [%0], [%1], 16;"
                                     :: "r"(smem_u32(dst)), "l"(src) : "memory");
                    }
                }
            }
            asm volatile("cp.async.commit_group;\n\tcp.async.wait_group 0;" ::: "memory");
            __syncwarp();
        }

        // two m=32 halves share the part buffer
        #pragma unroll
        for (int half = 0; half < 2; half++) {
            float acc[2][6][4];
            #pragma unroll
            for (int mt = 0; mt < 2; mt++)
                #pragma unroll
                for (int nt = 0; nt < 6; nt++)
                    acc[mt][nt][0]=acc[mt][nt][1]=acc[mt][nt][2]=acc[mt][nt][3]=0.f;

            if (t > 0) {
                #pragma unroll
                for (int c = 0; c < 4; c++) {
                    const float* st = (c0 + c == hb) ? own
                                    : stage + (size_t)(c0 + c) * 64 * 20;
                    #pragma unroll
                    for (int s = 0; s < 2; s++) {
                        const int kk = s * 8;
                        #pragma unroll
                        for (int mt = 0; mt < 2; mt++) {
                            int r0 = half * 32 + mt * 16 + gID;
                            unsigned a[4];
                            a[0] = __float_as_uint(st[r0 * 20 + kk + tig]);
                            a[1] = __float_as_uint(st[(r0 + 8) * 20 + kk + tig]);
                            a[2] = __float_as_uint(st[r0 * 20 + kk + tig + 4]);
                            a[3] = __float_as_uint(st[(r0 + 8) * 20 + kk + tig + 4]);
                            #pragma unroll
                            for (int nt = 0; nt < 6; nt++)
                                mma_tf32(acc[mt][nt], a, breg[c * 2 + s][nt][0], breg[c * 2 + s][nt][1]);
                        }
                    }
                }
            }

            // partials to smem: part[warp][local batch 0..31][48 gate rows]
            float* pw = part + warp * 32 * 49;
            #pragma unroll
            for (int mt = 0; mt < 2; mt++)
                #pragma unroll
                for (int nt = 0; nt < 6; nt++) {
                    int c = nt * 8 + tig * 2;
                    int r = mt * 16 + gID;
                    pw[r * 49 + c]           = acc[mt][nt][0];
                    pw[r * 49 + c + 1]       = acc[mt][nt][1];
                    pw[(r + 8) * 49 + c]     = acc[mt][nt][2];
                    pw[(r + 8) * 49 + c + 1] = acc[mt][nt][3];
                }
            __syncthreads();

            // gates: 2 outputs per thread this half (batches bb+16q, q=2*half+sub)
            #pragma unroll
            for (int sub = 0; sub < 2; sub++) {
                int lb = bb + 16 * sub;            // local batch within half
                int q  = half * 2 + sub;           // global quarter
                int gbatch = bb + 16 * q;
                float hr = b_s[uu], hz = b_s[16 + uu], hn = b_s[32 + uu];
                #pragma unroll
                for (int w = 0; w < 8; w++) {
                    const float* p = part + (w * 32 + lb) * 49;
                    hr += p[uu]; hz += p[16 + uu]; hn += p[32 + uu];
                }
                float ar = xr[q] + hr; ar = fminf(fmaxf(ar, -30.f), 30.f);
                float az = xz[q] + hz; az = fminf(fmaxf(az, -30.f), 30.f);
                float r = __fdividef(1.f, 1.f + __expf(-ar));
                float z = __fdividef(1.f, 1.f + __expf(-az));
                float an = xn[q] + r * hn; an = fminf(fmaxf(an, -15.f), 15.f);
                float n = 1.f - __fdividef(2.f, __expf(2.f * an) + 1.f);
                float hnew = (1.f - z) * n + z * hprev[q];
                float hro = to_tf32(hnew);
                hprev[q] = hro;
                y[((size_t)t * Bb + gbatch) * Hh + ug] = hro;
                own[gbatch * 20 + uu] = hro;
            }
            __syncthreads();                       // part/own reuse boundary
        }

        if (tid == 0) {
            unsigned nv = (unsigned)t + 1u;
            asm volatile("st.global.release.gpu.b32 [%0], %1;"
                         :: "l"(&g_hf[L][hb].v), "r"(nv) : "memory");
        }
    }
}

// ---------------- xg1 gemm-worker role: stream xg1[t] = y0[t] @ w_ih1^T + b --
// One block computes the full 64x1536 tile for one t; NWK blocks stride over t.
__device__ void gemmx_role(int gb, float* sm,
                           const float* __restrict__ wih1,
                           const float* __restrict__ bih1)
{
    float* As = sm;                 // 64*516
    float* Ws = sm + 64 * 516;      // 64*132
    const int tid  = threadIdx.x;
    const int warp = tid >> 5, lane = tid & 31;
    const int gID  = lane >> 2, tig = lane & 3;
    const int wm   = warp >> 2, wn = warp & 3;

    for (int t = gb; t < Tt; t += NWK) {
        // wait for y0[t]: all 32 layer-0 block flags >= t+1
        if (tid < 32) waitflag(&g_hf[0][tid].v, (unsigned)(t + 1));
        __syncthreads();

        // load full A = y0[t] (64 x 512), already tf32-valued
        const float* ysrc = g_y0 + (size_t)t * Bb * Hh;
        #pragma unroll
        for (int i = 0; i < 32; i++) {
            int idx = tid + i * 256;
            int r = idx >> 7, cb = idx & 127;
            *(float4*)(As + r * 516 + cb * 4) = *(const float4*)(ysrc + (size_t)r * Hh + cb * 4);
        }
        __syncthreads();

        for (int n0 = 0; n0 < 24; n0++) {
            float acc[2][2][4];
            #pragma unroll
            for (int mt = 0; mt < 2; mt++)
                #pragma unroll
                for (int nt = 0; nt < 2; nt++)
                    acc[mt][nt][0]=acc[mt][nt][1]=acc[mt][nt][2]=acc[mt][nt][3]=0.f;

            for (int kc = 0; kc < 4; kc++) {
                #pragma unroll
                for (int i = 0; i < 8; i++) {
                    int idx = tid + i * 256;
                    int r = idx >> 5, cb = idx & 31;
                    float4 v = *(const float4*)(wih1 + (size_t)(n0 * 64 + r) * Hh + kc * 128 + cb * 4);
                    *(float4*)(Ws + r * 132 + cb * 4) =
                        make_float4(to_tf32(v.x), to_tf32(v.y), to_tf32(v.z), to_tf32(v.w));
                }
                __syncthreads();
                #pragma unroll
                for (int ks = 0; ks < 16; ks++) {
                    int kA = kc * 128 + ks * 8, kW = ks * 8;
                    unsigned a[2][4];
                    #pragma unroll
                    for (int mt = 0; mt < 2; mt++) {
                        int r = wm * 32 + mt * 16 + gID;
                        a[mt][0] = __float_as_uint(As[r * 516 + kA + tig]);
                        a[mt][1] = __float_as_uint(As[(r + 8) * 516 + kA + tig]);
                        a[mt][2] = __float_as_uint(As[r * 516 + kA + tig + 4]);
                        a[mt][3] = __float_as_uint(As[(r + 8) * 516 + kA + tig + 4]);
                    }
                    #pragma unroll
                    for (int nt = 0; nt < 2; nt++) {
                        int nr = wn * 16 + nt * 8 + gID;
                        unsigned b0 = __float_as_uint(Ws[nr * 132 + kW + tig]);
                        unsigned b1 = __float_as_uint(Ws[nr * 132 + kW + tig + 4]);
                        #pragma unroll
                        for (int mt = 0; mt < 2; mt++)
                            mma_tf32(acc[mt][nt], a[mt], b0, b1);
                    }
                }
                __syncthreads();
            }
            #pragma unroll
            for (int mt = 0; mt < 2; mt++)
                #pragma unroll
                for (int rr = 0; rr < 2; rr++) {
                    int m = wm * 32 + mt * 16 + rr * 8 + gID;
                    #pragma unroll
                    for (int nt = 0; nt < 2; nt++) {
                        int n = n0 * 64 + wn * 16 + nt * 8 + tig * 2;
                        g_xg1[((size_t)t * Bb + m) * G3 + n]     = acc[mt][nt][rr * 2]     + bih1[n];
                        g_xg1[((size_t)t * Bb + m) * G3 + n + 1] = acc[mt][nt][rr * 2 + 1] + bih1[n + 1];
                    }
                }
        }
        __syncthreads();
        if (tid == 0)
            asm volatile("st.global.release.gpu.b32 [%0], %1;"
                         :: "l"(&g_xf[t]), "r"(1u) : "memory");
    }
}

// ---------------- megakernel: 32 L0-rec + 32 L1-rec + NWK xg1-workers ------
#define MEGA_SMEM ((ST_F + OWN_F + PART_F + 48) * 4)   // 219,328 B

__global__ __launch_bounds__(256, 1) void gru_mega(
    const float* __restrict__ whh0, const float* __restrict__ bhh0,
    const float* __restrict__ whh1, const float* __restrict__ bhh1,
    const float* __restrict__ wih1, const float* __restrict__ bih1)
{
    extern __shared__ float sm[];
    int bid = blockIdx.x;
    if (bid < 32)      rec_role(0, bid,      sm, g_xg0, whh0, bhh0, g_y0);
    else if (bid < 64) rec_role(1, bid - 32, sm, g_xg1, whh1, bhh1, g_y1);
    else               gemmx_role(bid - 64, sm, wih1, bih1);
}

// ---------------- launch ----------------
extern "C" void kernel_launch(void* const* d_in, const int* in_sizes, int n_in,
                              void* d_out, int out_size)
{
    const float* x    = (const float*)d_in[0];
    const float* wih0 = (const float*)d_in[1];
    const float* whh0 = (const float*)d_in[2];
    const float* bih0 = (const float*)d_in[3];
    const float* bhh0 = (const float*)d_in[4];
    const float* wih1 = (const float*)d_in[5];
    const float* whh1 = (const float*)d_in[6];
    const float* bih1 = (const float*)d_in[7];
    const float* bhh1 = (const float*)d_in[8];
    const float* fcw  = (const float*)d_in[9];
    const float* fcb  = (const float*)d_in[10];
    float* out = (float*)d_out;

    float *xg0p = 0, *y1p = 0;
    cudaGetSymbolAddress((void**)&xg0p, g_xg0);
    cudaGetSymbolAddress((void**)&y1p,  g_y1);

    cudaFuncSetAttribute(gru_mega, cudaFuncAttributeMaxDynamicSharedMemorySize, MEGA_SMEM);

    // reset all flags (replay-safe absolute targets)
    zero_flags<<<1, 256>>>();
    // xg0 = x @ w_ih0^T + b_ih0, written time-major (mode 1)
    gemm_tf32<<<dim3(G3 / 64, MM / 128), 256>>>(x, wih0, bih0, xg0p, MM, G3, Ii, 1);
    // fused: layer-0 rec || xg1 streaming gemm || layer-1 rec
    gru_mega<<<64 + NWK, 256, MEGA_SMEM>>>(whh0, bhh0, whh1, bhh1, wih1, bih1);
    // FC: y1 rows (t*B+b) -> out rows (b*T+t)  (mode 2)
    gemm_tf32<<<dim3(Ii / 64, MM / 128), 256>>>(y1p, fcw, fcb, out, MM, Ii, Hh, 2);
}

// round 16
// speedup vs baseline: 1.2863x; 1.0761x over previous
#include <cuda_runtime.h>
#include <cstdint>

#define Bb 64
#define Tt 1024
#define Ii 64
#define Hh 512
#define G3 1536
#define MM (Bb*Tt)      // 65536 rows
#define NWK 18          // xg1 gemm-worker blocks (64+64+18 = 146 <= 148 SMs)

// ---------------- scratch (device globals: allocation-free) ----------------
__device__ float g_xg0[(size_t)MM * G3];   // layer-0 input gates (time-major rows t*B+b)
__device__ float g_xg1[(size_t)MM * G3];   // layer-1 input gates (time-major)
__device__ float g_y0 [(size_t)MM * Hh];   // layer-0 hidden history (time-major)
__device__ float g_y1 [(size_t)MM * Hh];   // layer-1 hidden history (time-major)
__device__ float g_wr [(size_t)G3 * Hh];   // w_ih1 pre-rounded to tf32 (3 MB)

struct __align__(128) PadFlag { unsigned v; unsigned pad[31]; };
__device__ PadFlag g_hf[2][2][32];   // [layer][grp][hb] step flags (zeroed per launch)
__device__ unsigned g_xf[Tt];        // xg1[t] ready flags (zeroed per launch)

// ---------------- helpers ----------------
__device__ __forceinline__ float to_tf32(float x) {
    unsigned u;
    asm("cvt.rna.tf32.f32 %0, %1;" : "=r"(u) : "f"(x));
    return __uint_as_float(u);
}

__device__ __forceinline__ void mma_tf32(float* c, const unsigned* a, unsigned b0, unsigned b1) {
    asm("mma.sync.aligned.m16n8k8.row.col.f32.tf32.tf32.f32 "
        "{%0,%1,%2,%3},{%4,%5,%6,%7},{%8,%9},{%0,%1,%2,%3};"
        : "+f"(c[0]), "+f"(c[1]), "+f"(c[2]), "+f"(c[3])
        : "r"(a[0]), "r"(a[1]), "r"(a[2]), "r"(a[3]), "r"(b0), "r"(b1));
}

__device__ __forceinline__ unsigned smem_u32(const void* p) {
    return (unsigned)__cvta_generic_to_shared(p);
}

__device__ __forceinline__ void waitflag(const unsigned* p, unsigned tgt) {
    unsigned v;
    do {
        asm volatile("ld.global.acquire.gpu.b32 %0, [%1];" : "=r"(v) : "l"(p) : "memory");
    } while ((int)(v - tgt) < 0);
}

// ---------------- prologue: zero flags + pre-round w_ih1 to tf32 -----------
__global__ void prep(const float* __restrict__ wih1) {
    int gid = blockIdx.x * blockDim.x + threadIdx.x;
    if (blockIdx.x == 0 && threadIdx.x < 128) ((PadFlag*)g_hf)[threadIdx.x].v = 0;
    for (int i = gid; i < Tt; i += gridDim.x * blockDim.x) g_xf[i] = 0;
    for (int i = gid; i < G3 * Hh; i += gridDim.x * blockDim.x) g_wr[i] = to_tf32(wih1[i]);
}

// ---------------- generic tf32 GEMM (xg0 + FC): C = A @ W^T + bias ----------
// mode: output row remap. 0: ro=m  1: m=(b*T+t) -> ro=t*B+b   2: m=(t*B+b) -> ro=b*T+t
__global__ __launch_bounds__(256) void gemm_tf32(
    const float* __restrict__ A, const float* __restrict__ W,
    const float* __restrict__ bias, float* __restrict__ C,
    int M, int N, int K, int mode)
{
    __shared__ float As[128][20];
    __shared__ float Ws[64][20];
    const int tid  = threadIdx.x;
    const int warp = tid >> 5, lane = tid & 31;
    const int gID  = lane >> 2, tig = lane & 3;
    const int wm   = warp >> 1, wn = warp & 1;
    const int m0   = blockIdx.y * 128, n0 = blockIdx.x * 64;

    float acc[2][4][4];
    #pragma unroll
    for (int i = 0; i < 2; i++)
        #pragma unroll
        for (int j = 0; j < 4; j++)
            #pragma unroll
            for (int q = 0; q < 4; q++) acc[i][j][q] = 0.f;

    for (int k0 = 0; k0 < K; k0 += 16) {
        #pragma unroll
        for (int i = 0; i < 2; i++) {
            int idx = tid + i * 256;
            int r = idx >> 2, cb = idx & 3;
            float4 v = *(const float4*)(A + (size_t)(m0 + r) * K + k0 + cb * 4);
            *(float4*)(&As[r][cb * 4]) =
                make_float4(to_tf32(v.x), to_tf32(v.y), to_tf32(v.z), to_tf32(v.w));
        }
        {
            int r = tid >> 2, cb = tid & 3;
            float4 v = *(const float4*)(W + (size_t)(n0 + r) * K + k0 + cb * 4);
            *(float4*)(&Ws[r][cb * 4]) =
                make_float4(to_tf32(v.x), to_tf32(v.y), to_tf32(v.z), to_tf32(v.w));
        }
        __syncthreads();
        #pragma unroll
        for (int s = 0; s < 2; s++) {
            const int kk = s * 8;
            unsigned a[2][4];
            #pragma unroll
            for (int mt = 0; mt < 2; mt++) {
                int r = wm * 32 + mt * 16 + gID;
                a[mt][0] = __float_as_uint(As[r][kk + tig]);
                a[mt][1] = __float_as_uint(As[r + 8][kk + tig]);
                a[mt][2] = __float_as_uint(As[r][kk + tig + 4]);
                a[mt][3] = __float_as_uint(As[r + 8][kk + tig + 4]);
            }
            #pragma unroll
            for (int nt = 0; nt < 4; nt++) {
                int n = wn * 32 + nt * 8 + gID;
                unsigned b0 = __float_as_uint(Ws[n][kk + tig]);
                unsigned b1 = __float_as_uint(Ws[n][kk + tig + 4]);
                #pragma unroll
                for (int mt = 0; mt < 2; mt++)
                    mma_tf32(acc[mt][nt], a[mt], b0, b1);
            }
        }
        __syncthreads();
    }
    #pragma unroll
    for (int mt = 0; mt < 2; mt++) {
        #pragma unroll
        for (int rr = 0; rr < 2; rr++) {
            int r = m0 + wm * 32 + mt * 16 + rr * 8 + gID;
            int ro = (mode == 0) ? r
                   : (mode == 1) ? ((r & (Tt - 1)) * Bb + (r >> 10))
                                 : ((r & (Bb - 1)) * Tt + (r >> 6));
            #pragma unroll
            for (int nt = 0; nt < 4; nt++) {
                int c = n0 + wn * 32 + nt * 8 + tig * 2;
                C[(size_t)ro * N + c]     = acc[mt][nt][rr * 2]     + bias[c];
                C[(size_t)ro * N + c + 1] = acc[mt][nt][rr * 2 + 1] + bias[c + 1];
            }
        }
    }
}

// ---------------- recurrent role (m=32 groups, 64 blocks per layer) --------
// rb: 0..63 -> grp = rb>>5 (32 batches), hb = rb&31 (16 units).
#define ST_F   (8*4*32*20)
#define OWN_F  (32*20)
#define PART_F (8*32*49)

__device__ __forceinline__ void rec_role(
    int L, int rb, float* sm,
    const float* __restrict__ xg, const float* __restrict__ whh,
    const float* __restrict__ bhh, float* __restrict__ y)
{
    float* stage = sm;
    float* own   = sm + ST_F;
    float* part  = own + OWN_F;
    float* b_s   = part + PART_F;

    const int grp = rb >> 5, hb = rb & 31;
    const int tid  = threadIdx.x;
    const int warp = tid >> 5, lane = tid & 31;
    const int gID  = lane >> 2, tig = lane & 3;
    const int bb   = tid >> 4, uu = tid & 15;
    const int bglob = grp * 32;
    const int k0w  = warp * 64;
    const int c0   = warp * 4;

    unsigned breg[8][6][2];
    #pragma unroll
    for (int nt = 0; nt < 6; nt++) {
        int r = nt * 8 + gID;                          // 0..47
        int grow = (r >> 4) * Hh + hb * 16 + (r & 15);
        const float* wrow = whh + (size_t)grow * Hh;
        #pragma unroll
        for (int ks = 0; ks < 8; ks++) {
            int k = k0w + ks * 8 + tig;
            breg[ks][nt][0] = __float_as_uint(to_tf32(wrow[k]));
            breg[ks][nt][1] = __float_as_uint(to_tf32(wrow[k + 4]));
        }
    }
    if (tid < 48) b_s[tid] = bhh[(tid >> 4) * Hh + hb * 16 + (tid & 15)];
    __syncthreads();

    const int ug = hb * 16 + uu;
    float hprev[2] = {0.f, 0.f};

    for (int t = 0; t < Tt; t++) {
        if (L == 1) {
            if (lane == 0) waitflag(&g_xf[t], 1u);
            __syncwarp();
        }
        const size_t xb0 = ((size_t)t * Bb + bglob + bb) * (size_t)G3;
        const size_t xb1 = xb0 + (size_t)16 * G3;
        float xr0 = __ldg(xg + xb0 + ug);
        float xz0 = __ldg(xg + xb0 + Hh + ug);
        float xn0 = __ldg(xg + xb0 + 2 * Hh + ug);
        float xr1 = __ldg(xg + xb1 + ug);
        float xz1 = __ldg(xg + xb1 + Hh + ug);
        float xn1 = __ldg(xg + xb1 + 2 * Hh + ug);

        float acc[2][6][4];
        #pragma unroll
        for (int mt = 0; mt < 2; mt++)
            #pragma unroll
            for (int nt = 0; nt < 6; nt++)
                acc[mt][nt][0]=acc[mt][nt][1]=acc[mt][nt][2]=acc[mt][nt][3]=0.f;

        if (t > 0) {
            const float* ybase = y + ((size_t)(t - 1) * Bb + bglob) * Hh;
            if (lane < 4) {
                int j = c0 + lane;
                if (j != hb) waitflag(&g_hf[L][grp][j].v, (unsigned)t);
            }
            __syncwarp();
            #pragma unroll
            for (int c = 0; c < 4; c++) {
                int j = c0 + c;
                if (j != hb) {
                    #pragma unroll
                    for (int i = 0; i < 4; i++) {
                        int idx = lane + 32 * i;
                        int row = idx >> 2, seg = idx & 3;
                        const float* src = ybase + (size_t)row * Hh + j * 16 + seg * 4;
                        float* dst = stage + (((warp * 4 + c) * 32 + row) * 20 + seg * 4);
                        asm volatile("cp.async.cg.shared.global [%0], [%1], 16;"
                                     :: "r"(smem_u32(dst)), "l"(src) : "memory");
                    }
                }
            }
            asm volatile("cp.async.commit_group;\n\tcp.async.wait_group 0;" ::: "memory");
            __syncwarp();

            #pragma unroll
            for (int c = 0; c < 4; c++) {
                const float* st = (c0 + c == hb) ? own
                                : stage + ((warp * 4 + c) * 32 * 20);
                #pragma unroll
                for (int s = 0; s < 2; s++) {
                    const int kk = s * 8;
                    #pragma unroll
                    for (int mt = 0; mt < 2; mt++) {
                        unsigned a[4];
                        int r0 = gID + 16 * mt;
                        a[0] = __float_as_uint(st[r0 * 20 + kk + tig]);
                        a[1] = __float_as_uint(st[(r0 + 8) * 20 + kk + tig]);
                        a[2] = __float_as_uint(st[r0 * 20 + kk + tig + 4]);
                        a[3] = __float_as_uint(st[(r0 + 8) * 20 + kk + tig + 4]);
                        #pragma unroll
                        for (int nt = 0; nt < 6; nt++)
                            mma_tf32(acc[mt][nt], a, breg[c * 2 + s][nt][0], breg[c * 2 + s][nt][1]);
                    }
                }
            }
        }

        float* pw = part + warp * 32 * 49;
        #pragma unroll
        for (int mt = 0; mt < 2; mt++)
            #pragma unroll
            for (int nt = 0; nt < 6; nt++) {
                int c = nt * 8 + tig * 2;
                int r0 = gID + 16 * mt;
                pw[r0 * 49 + c]           = acc[mt][nt][0];
                pw[r0 * 49 + c + 1]       = acc[mt][nt][1];
                pw[(r0 + 8) * 49 + c]     = acc[mt][nt][2];
                pw[(r0 + 8) * 49 + c + 1] = acc[mt][nt][3];
            }
        __syncthreads();

        #pragma unroll
        for (int half = 0; half < 2; half++) {
            int bbx = bb + 16 * half;
            float hr = b_s[uu], hz = b_s[16 + uu], hn = b_s[32 + uu];
            #pragma unroll
            for (int w = 0; w < 8; w++) {
                const float* p = part + (w * 32 + bbx) * 49;
                hr += p[uu]; hz += p[16 + uu]; hn += p[32 + uu];
            }
            float xr = half ? xr1 : xr0, xz = half ? xz1 : xz0, xn = half ? xn1 : xn0;
            float ar = xr + hr; ar = fminf(fmaxf(ar, -30.f), 30.f);
            float az = xz + hz; az = fminf(fmaxf(az, -30.f), 30.f);
            float r = __fdividef(1.f, 1.f + __expf(-ar));
            float z = __fdividef(1.f, 1.f + __expf(-az));
            float an = xn + r * hn; an = fminf(fmaxf(an, -15.f), 15.f);
            float n = 1.f - __fdividef(2.f, __expf(2.f * an) + 1.f);
            float hnew = (1.f - z) * n + z * hprev[half];
            float hro = to_tf32(hnew);
            hprev[half] = hro;
            y[((size_t)t * Bb + bglob + bbx) * Hh + ug] = hro;
            own[bbx * 20 + uu] = hro;
        }

        __syncthreads();
        if (tid == 0) {
            unsigned nv = (unsigned)t + 1u;
            asm volatile("st.global.release.gpu.b32 [%0], %1;"
                         :: "l"(&g_hf[L][grp][hb].v), "r"(nv) : "memory");
        }
    }
}

// ---------------- xg1 worker: double-buffered tf32 GEMM per timestep -------
// xg1[t] (64x1536) = y0[t] (64x512) @ w_r^T + b_ih1.  NWK blocks stride over t.
// smem: As[64][516] | Ws[2][128][68].  Warps: 2m x 4n.  W pre-rounded (g_wr).
#define WK_AS  (64*516)
#define WK_WS  (128*68)

__device__ void gemmx_role(int gb, float* sm, const float* __restrict__ bih1)
{
    float* As = sm;
    float* Ws = sm + WK_AS;
    const int tid  = threadIdx.x;
    const int lane = tid & 31, warp = tid >> 5;
    const int gID  = lane >> 2, tig = lane & 3;
    const int wm   = warp >> 2, wn = warp & 3;

    for (int t = gb; t < Tt; t += NWK) {
        // y0[t] complete: all 64 layer-0 flags >= t+1
        if (tid < 64) waitflag(&g_hf[0][tid >> 5][tid & 31].v, (unsigned)(t + 1));
        __syncthreads();

        // stage A = y0[t] (already tf32-valued): 64 rows x 512 floats = 8192 float4s
        const float* ysrc = g_y0 + (size_t)t * Bb * Hh;
        #pragma unroll
        for (int i = 0; i < 32; i++) {
            int idx = tid + i * 256;
            int r = idx >> 7, cb = idx & 127;        // row 0..63, seg 0..127 (x4 floats)
            asm volatile("cp.async.cg.shared.global [%0], [%1], 16;"
                         :: "r"(smem_u32(As + r * 516 + cb * 4)),
                            "l"(ysrc + (size_t)r * Hh + cb * 4) : "memory");
        }
        asm volatile("cp.async.commit_group;" ::: "memory");

        for (int n0 = 0; n0 < 12; n0++) {      // 12 n-tiles of 128 rows
            const float* wbase = g_wr + (size_t)(n0 * 128) * Hh;
            // prologue: chunk kc=0 -> buf 0
            #pragma unroll
            for (int i = 0; i < 8; i++) {
                int idx = tid + i * 256;       // 2048 float4s: 128 rows x 16 segs
                int r = idx >> 4, cb = idx & 15;
                asm volatile("cp.async.cg.shared.global [%0], [%1], 16;"
                             :: "r"(smem_u32(Ws + r * 68 + cb * 4)),
                                "l"(wbase + (size_t)r * Hh + cb * 4) : "memory");
            }
            asm volatile("cp.async.commit_group;" ::: "memory");

            float acc[2][4][4];
            #pragma unroll
            for (int mt = 0; mt < 2; mt++)
                #pragma unroll
                for (int nt = 0; nt < 4; nt++)
                    acc[mt][nt][0]=acc[mt][nt][1]=acc[mt][nt][2]=acc[mt][nt][3]=0.f;

            for (int kc = 0; kc < 8; kc++) {   // k-chunks of 64
                if (kc < 7) {                  // prefetch next chunk
                    #pragma unroll
                    for (int i = 0; i < 8; i++) {
                        int idx = tid + i * 256;
                        int r = idx >> 4, cb = idx & 15;
                        asm volatile("cp.async.cg.shared.global [%0], [%1], 16;"
                                     :: "r"(smem_u32(Ws + ((kc + 1) & 1) * WK_WS + r * 68 + cb * 4)),
                                        "l"(wbase + (size_t)r * Hh + (kc + 1) * 64 + cb * 4) : "memory");
                    }
                    asm volatile("cp.async.commit_group;\n\tcp.async.wait_group 1;" ::: "memory");
                } else {
                    asm volatile("cp.async.wait_group 0;" ::: "memory");
                }
                __syncthreads();               // chunk kc visible to all
                const float* W = Ws + (kc & 1) * WK_WS;
                #pragma unroll
                for (int ks = 0; ks < 8; ks++) {
                    int kA = kc * 64 + ks * 8, kW = ks * 8;
                    unsigned a[2][4];
                    #pragma unroll
                    for (int mt = 0; mt < 2; mt++) {
                        int r = wm * 32 + mt * 16 + gID;
                        a[mt][0] = __float_as_uint(As[r * 516 + kA + tig]);
                        a[mt][1] = __float_as_uint(As[(r + 8) * 516 + kA + tig]);
                        a[mt][2] = __float_as_uint(As[r * 516 + kA + tig + 4]);
                        a[mt][3] = __float_as_uint(As[(r + 8) * 516 + kA + tig + 4]);
                    }
                    #pragma unroll
                    for (int nt = 0; nt < 4; nt++) {
                        int nr = wn * 32 + nt * 8 + gID;
                        unsigned b0 = __float_as_uint(W[nr * 68 + kW + tig]);
                        unsigned b1 = __float_as_uint(W[nr * 68 + kW + tig + 4]);
                        #pragma unroll
                        for (int mt = 0; mt < 2; mt++)
                            mma_tf32(acc[mt][nt], a[mt], b0, b1);
                    }
                }
                __syncthreads();               // buffer consumed; safe to refill
            }
            // epilogue
            #pragma unroll
            for (int mt = 0; mt < 2; mt++)
                #pragma unroll
                for (int rr = 0; rr < 2; rr++) {
                    int m = wm * 32 + mt * 16 + rr * 8 + gID;
                    #pragma unroll
                    for (int nt = 0; nt < 4; nt++) {
                        int n = n0 * 128 + wn * 32 + nt * 8 + tig * 2;
                        float* dst = g_xg1 + ((size_t)t * Bb + m) * G3 + n;
                        dst[0] = acc[mt][nt][rr * 2]     + __ldg(bih1 + n);
                        dst[1] = acc[mt][nt][rr * 2 + 1] + __ldg(bih1 + n + 1);
                    }
                }
        }
        __syncthreads();
        if (tid == 0)
            asm volatile("st.global.release.gpu.b32 [%0], %1;"
                         :: "l"(&g_xf[t]), "r"(1u) : "memory");
    }
}

// ---------------- megakernel: 64 L0-rec + 64 L1-rec + 18 workers -----------
#define MEGA_SMEM ((WK_AS + 2*WK_WS) * 4)   // 201,728 B (> rec's 134,848)

__global__ __launch_bounds__(256, 1) void gru_mega(
    const float* __restrict__ whh0, const float* __restrict__ bhh0,
    const float* __restrict__ whh1, const float* __restrict__ bhh1,
    const float* __restrict__ bih1)
{
    extern __shared__ float sm[];
    int bid = blockIdx.x;
    if (bid < 64)       rec_role(0, bid,      sm, g_xg0, whh0, bhh0, g_y0);
    else if (bid < 128) rec_role(1, bid - 64, sm, g_xg1, whh1, bhh1, g_y1);
    else                gemmx_role(bid - 128, sm, bih1);
}

// ---------------- launch ----------------
extern "C" void kernel_launch(void* const* d_in, const int* in_sizes, int n_in,
                              void* d_out, int out_size)
{
    const float* x    = (const float*)d_in[0];
    const float* wih0 = (const float*)d_in[1];
    const float* whh0 = (const float*)d_in[2];
    const float* bih0 = (const float*)d_in[3];
    const float* bhh0 = (const float*)d_in[4];
    const float* wih1 = (const float*)d_in[5];
    const float* whh1 = (const float*)d_in[6];
    const float* bih1 = (const float*)d_in[7];
    const float* bhh1 = (const float*)d_in[8];
    const float* fcw  = (const float*)d_in[9];
    const float* fcb  = (const float*)d_in[10];
    float* out = (float*)d_out;

    float *xg0p = 0, *y1p = 0;
    cudaGetSymbolAddress((void**)&xg0p, g_xg0);
    cudaGetSymbolAddress((void**)&y1p,  g_y1);

    cudaFuncSetAttribute(gru_mega, cudaFuncAttributeMaxDynamicSharedMemorySize, MEGA_SMEM);

    // reset flags + pre-round w_ih1 to tf32
    prep<<<256, 256>>>(wih1);
    // xg0 = x @ w_ih0^T + b_ih0, written time-major (mode 1)
    gemm_tf32<<<dim3(G3 / 64, MM / 128), 256>>>(x, wih0, bih0, xg0p, MM, G3, Ii, 1);
    // fused: layer-0 rec || xg1 streaming gemm || layer-1 rec
    gru_mega<<<128 + NWK, 256, MEGA_SMEM>>>(whh0, bhh0, whh1, bhh1, bih1);
    // FC: y1 rows (t*B+b) -> out rows (b*T+t)  (mode 2)
    gemm_tf32<<<dim3(Ii / 64, MM / 128), 256>>>(y1p, fcw, fcb, out, MM, Ii, Hh, 2);
}